// round 1
// baseline (speedup 1.0000x reference)
#include <cuda_runtime.h>
#include <cuda_bf16.h>
#include <cstdint>

// Problem: y[b,e] = relu(sum_a action[b,a] * conv_w[e,a] + conv_b[e])
// out[b,e,h,w] = y[b,e] broadcast over 64x64 spatial.
// B=128, A=256, E=256, H=W=64. Output fp32, 128*256*4096 = 134,217,728 floats.

#define B_DIM 128
#define A_DIM 256
#define E_DIM 256
#define HW    4096   // 64*64

// Scratch for the small GEMM result (128 KB). Device global: allowed.
__device__ float g_y[B_DIM * E_DIM];

// ---------------------------------------------------------------------------
// Kernel 1: tiny GEMM + bias + relu. One block per batch row, one thread per
// output channel e. action row staged in shared; conv_w read via float4 LDG
// (fully L1/L2 resident after first touch; total traffic trivial).
// ---------------------------------------------------------------------------
__global__ __launch_bounds__(E_DIM)
void action_gemm_kernel(const float* __restrict__ action,
                        const float* __restrict__ conv_w,
                        const float* __restrict__ conv_b)
{
    __shared__ float s_act[A_DIM];
    const int b = blockIdx.x;      // 0..127
    const int e = threadIdx.x;     // 0..255

    s_act[e] = action[b * A_DIM + e];
    __syncthreads();

    const float4* w4 = reinterpret_cast<const float4*>(conv_w + e * A_DIM);
    const float4* a4 = reinterpret_cast<const float4*>(s_act);

    float sum = 0.0f;
#pragma unroll
    for (int i = 0; i < A_DIM / 4; ++i) {
        float4 wv = w4[i];
        float4 av = a4[i];   // broadcast from shared (conflict-free)
        sum = fmaf(wv.x, av.x, sum);
        sum = fmaf(wv.y, av.y, sum);
        sum = fmaf(wv.z, av.z, sum);
        sum = fmaf(wv.w, av.w, sum);
    }
    sum += conv_b[e];
    g_y[b * E_DIM + e] = fmaxf(sum, 0.0f);
}

// ---------------------------------------------------------------------------
// Kernel 2: broadcast fill. One block per (b,e) plane (4096 contiguous
// floats = 1024 float4). 256 threads * 4 float4 stores each, coalesced
// STG.128 with streaming hint (write-once data, don't pollute L2).
// ---------------------------------------------------------------------------
__global__ __launch_bounds__(256)
void broadcast_fill_kernel(float4* __restrict__ out)
{
    const int plane = blockIdx.x;                 // 0 .. 32767 == b*256 + e
    const float v = g_y[plane];                   // uniform per block (L2 hit)
    const float4 v4 = make_float4(v, v, v, v);

    float4* p = out + (size_t)plane * (HW / 4);   // 1024 float4 per plane
    const int t = threadIdx.x;

    __stcs(p + t,        v4);
    __stcs(p + t + 256,  v4);
    __stcs(p + t + 512,  v4);
    __stcs(p + t + 768,  v4);
}

extern "C" void kernel_launch(void* const* d_in, const int* in_sizes, int n_in,
                              void* d_out, int out_size)
{
    const float* action = (const float*)d_in[0];   // [128, 256]
    const float* conv_w = (const float*)d_in[1];   // [256, 256]
    const float* conv_b = (const float*)d_in[2];   // [256]
    float4* out = (float4*)d_out;                  // [128, 256, 64, 64] fp32

    action_gemm_kernel<<<B_DIM, E_DIM>>>(action, conv_w, conv_b);
    broadcast_fill_kernel<<<B_DIM * E_DIM, 256>>>(out);
}